// round 16
// baseline (speedup 1.0000x reference)
#include <cuda_runtime.h>
#include <cuda_bf16.h>
#include <cuda_fp16.h>
#include <math.h>
#include <stdint.h>

#define SQ 2048
#define BB 2
#define DD 1024
#define HH 16
#define CC 64
#define HC 1024
#define NROW 4096

typedef unsigned long long ull;
typedef unsigned int u32;

__device__ __forceinline__ float ex2f(float x) {
    float y; asm("ex2.approx.f32 %0, %1;" : "=f"(y) : "f"(x)); return y;
}
__device__ __forceinline__ u32 smem_u32(const void* p) {
    u32 a;
    asm("{ .reg .u64 t; cvta.to.shared.u64 t, %1; cvt.u32.u64 %0, t; }"
        : "=r"(a) : "l"(p));
    return a;
}
__device__ __forceinline__ void ldsm4(u32 &r0, u32 &r1, u32 &r2, u32 &r3, u32 addr) {
    asm volatile("ldmatrix.sync.aligned.m8n8.x4.shared.b16 {%0,%1,%2,%3}, [%4];"
                 : "=r"(r0), "=r"(r1), "=r"(r2), "=r"(r3) : "r"(addr));
}
__device__ __forceinline__ void ldsm4t(u32 &r0, u32 &r1, u32 &r2, u32 &r3, u32 addr) {
    asm volatile("ldmatrix.sync.aligned.m8n8.x4.trans.shared.b16 {%0,%1,%2,%3}, [%4];"
                 : "=r"(r0), "=r"(r1), "=r"(r2), "=r"(r3) : "r"(addr));
}
// bf16 MMA
__device__ __forceinline__ void hmma(float* d, const u32* a, const u32* b) {
    asm volatile(
        "mma.sync.aligned.m16n8k16.row.col.f32.bf16.bf16.f32 "
        "{%0,%1,%2,%3}, {%4,%5,%6,%7}, {%8,%9}, {%0,%1,%2,%3};"
        : "+f"(d[0]), "+f"(d[1]), "+f"(d[2]), "+f"(d[3])
        : "r"(a[0]), "r"(a[1]), "r"(a[2]), "r"(a[3]), "r"(b[0]), "r"(b[1]));
}
// fp16 MMA
__device__ __forceinline__ void hmma16(float* d, const u32* a, const u32* b) {
    asm volatile(
        "mma.sync.aligned.m16n8k16.row.col.f32.f16.f16.f32 "
        "{%0,%1,%2,%3}, {%4,%5,%6,%7}, {%8,%9}, {%0,%1,%2,%3};"
        : "+f"(d[0]), "+f"(d[1]), "+f"(d[2]), "+f"(d[3])
        : "r"(a[0]), "r"(a[1]), "r"(a[2]), "r"(a[3]), "r"(b[0]), "r"(b[1]));
}
__device__ __forceinline__ void cpasync16(u32 saddr, const void* g) {
    asm volatile("cp.async.cg.shared.global [%0], [%1], 16;"
                 :: "r"(saddr), "l"(g) : "memory");
}
#define CP_COMMIT() asm volatile("cp.async.commit_group;" ::: "memory")
#define CP_WAIT1()  asm volatile("cp.async.wait_group 1;" ::: "memory")
#define CP_WAIT0()  asm volatile("cp.async.wait_group 0;" ::: "memory")

#define SWZ(o) ((o) ^ (((o) >> 3) & 0x70))

// bf16 hi/lo split
__device__ __forceinline__ void split2(float a, float b, u32 &hp, u32 &lp) {
    __nv_bfloat16 ha = __float2bfloat16_rn(a), hb = __float2bfloat16_rn(b);
    float ra = a - __bfloat162float(ha);
    float rb = b - __bfloat162float(hb);
    __nv_bfloat16 la = __float2bfloat16_rn(ra), lb = __float2bfloat16_rn(rb);
    hp = (u32)__bfloat16_as_ushort(ha) | ((u32)__bfloat16_as_ushort(hb) << 16);
    lp = (u32)__bfloat16_as_ushort(la) | ((u32)__bfloat16_as_ushort(lb) << 16);
}
// fp16 hi/lo split
__device__ __forceinline__ void split2h(float a, float b, u32 &hp, u32 &lp) {
    __half ha = __float2half_rn(a), hb = __float2half_rn(b);
    float ra = a - __half2float(ha);
    float rb = b - __half2float(hb);
    __half la = __float2half_rn(ra), lb = __float2half_rn(rb);
    hp = (u32)__half_as_ushort(ha) | ((u32)__half_as_ushort(hb) << 16);
    lp = (u32)__half_as_ushort(la) | ((u32)__half_as_ushort(lb) << 16);
}
__device__ __forceinline__ u32 packh(float a, float b) {
    __half ha = __float2half_rn(a), hb = __float2half_rn(b);
    return (u32)__half_as_ushort(ha) | ((u32)__half_as_ushort(hb) << 16);
}

// ---------------- scratch (allocation-free) ---------------------------------
__device__ __nv_bfloat16 g_xh[(size_t)NROW*DD];
__device__ __nv_bfloat16 g_xl[(size_t)NROW*DD];
__device__ __nv_bfloat16 g_wth[(size_t)4*HC*DD];   // z: 0=q 1=k 2=v 3=out, [N][K]
__device__ __nv_bfloat16 g_wtl[(size_t)4*HC*DD];
__device__ __half g_qh[(size_t)BB*HH*SQ*CC];       // fp16 hi, pre-scaled by QS
__device__ __half g_ql[(size_t)BB*HH*SQ*CC];       // fp16 lo
__device__ __half g_kh[(size_t)BB*HH*SQ*CC];       // fp16 single
__device__ __nv_bfloat16 g_vh[(size_t)BB*HH*SQ*CC];
__device__ __nv_bfloat16 g_vl[(size_t)BB*HH*SQ*CC];
__device__ __nv_bfloat16 g_aoh[(size_t)NROW*HC];
__device__ __nv_bfloat16 g_aol[(size_t)NROW*HC];

#define QS 0.18033688011112042f   /* 0.125 * log2(e) */
#define MBc 23.083120654223414f   /* 16 * log2(e) */

// ---------------- prep kernels ----------------------------------------------
__global__ __launch_bounds__(256) void conv_x(const float* __restrict__ x)
{
    int i = blockIdx.x * 256 + threadIdx.x;
    float4 v = ((const float4*)x)[i];
    u32 h01, l01, h23, l23;
    split2(v.x, v.y, h01, l01);
    split2(v.z, v.w, h23, l23);
    ((uint2*)g_xh)[i] = make_uint2(h01, h23);
    ((uint2*)g_xl)[i] = make_uint2(l01, l23);
}

__global__ __launch_bounds__(256) void prep_w(
    const float* __restrict__ Wq, const float* __restrict__ Wk,
    const float* __restrict__ Wv, const float* __restrict__ Wo)
{
    const int z = blockIdx.z;
    const float* __restrict__ W = (z == 0) ? Wq : (z == 1) ? Wk : (z == 2) ? Wv : Wo;
    const int n0 = blockIdx.x * 32, k0 = blockIdx.y * 32;
    __shared__ float t[32][33];
    const int c = threadIdx.x & 31, r8 = threadIdx.x >> 5;
#pragma unroll
    for (int rr = 0; rr < 4; rr++) {
        int r = r8 + rr * 8;
        t[c][r] = W[(size_t)(k0 + r) * HC + n0 + c];
    }
    __syncthreads();
    __nv_bfloat16* oh = g_wth + (size_t)z * HC * DD;
    __nv_bfloat16* ol = g_wtl + (size_t)z * HC * DD;
#pragma unroll
    for (int rr = 0; rr < 4; rr++) {
        int r = r8 + rr * 8;
        float v = t[r][c];
        __nv_bfloat16 h = __float2bfloat16_rn(v);
        __nv_bfloat16 l = __float2bfloat16_rn(v - __bfloat162float(h));
        size_t o = (size_t)(n0 + r) * DD + k0 + c;
        oh[o] = h; ol[o] = l;
    }
}

// ---------------------------------------------------------------------------
// Kernel 1: fused QKV (3 projections per CTA) + RMSNorm + RoPE -> split stores
// grid = (HH, NROW/128), block = 256, 8 warps 4m x 2n, warp tile 32x32 per z.
// Stage (80KB): AH 0, AL 16K, then per z at 32K + z*16K: BH, BL(+8K). 2 stages.
// ---------------------------------------------------------------------------
#define QK_AH 0
#define QK_AL 16384
#define QK_B  32768
#define QK_STAGE 81920
#define QKV_SMEM (2*QK_STAGE)

struct EpiSmem { float outs[128][66]; float rstd[128]; };

#define QKV_ISSUE(chv, bb)                                                      \
    _Pragma("unroll")                                                           \
    for (int q = 0; q < 4; q++) {                                               \
        int idx = tid + q * 256;                                                \
        int row = idx >> 3, c16 = (idx & 7) << 4;                               \
        u32 so = SWZ(row * 128 + c16);                                          \
        size_t go = (size_t)row * 2048 + (size_t)(chv) * 128 + c16;             \
        cpasync16(sbase + (bb) + QK_AH + so, AhP + go);                         \
        cpasync16(sbase + (bb) + QK_AL + so, AlP + go);                         \
    }                                                                           \
    _Pragma("unroll")                                                           \
    for (int q = 0; q < 2; q++) {                                               \
        int idx = tid + q * 256;                                                \
        int row = idx >> 3, c16 = (idx & 7) << 4;                               \
        u32 so = SWZ(row * 128 + c16);                                          \
        size_t go = (size_t)row * 2048 + (size_t)(chv) * 128 + c16;             \
        _Pragma("unroll")                                                       \
        for (int z = 0; z < 3; z++) {                                           \
            cpasync16(sbase + (bb) + QK_B + z * 16384 + so,        BhP[z] + go);\
            cpasync16(sbase + (bb) + QK_B + z * 16384 + 8192 + so, BlP[z] + go);\
        }                                                                       \
    }

__global__ __launch_bounds__(256, 1) void qkv_hmma(
    const float* __restrict__ rope, const float* __restrict__ qw,
    const float* __restrict__ kw)
{
    extern __shared__ __align__(128) char smc[];
    EpiSmem* ep = (EpiSmem*)smc;
    const u32 sbase = smem_u32(smc);

    const int tid = threadIdx.x;
    const int l = tid & 31, w = tid >> 5;
    const int wr = w >> 1, wc = w & 1;
    const int h = blockIdx.x, r0 = blockIdx.y * 128;
    const int n0 = h * CC;

    const char* AhP = (const char*)(g_xh + (size_t)r0 * DD);
    const char* AlP = (const char*)(g_xl + (size_t)r0 * DD);
    const char* BhP[3]; const char* BlP[3];
#pragma unroll
    for (int z = 0; z < 3; z++) {
        BhP[z] = (const char*)(g_wth + (size_t)z * HC * DD + (size_t)n0 * DD);
        BlP[z] = (const char*)(g_wtl + (size_t)z * HC * DD + (size_t)n0 * DD);
    }

    const int aRowL = ((l >> 3) & 1) * 8 + (l & 7);
    const int aColL = (l >> 4) * 16;
    const int bRowL = (l >> 4) * 8 + (l & 7);
    const int bColL = ((l >> 3) & 1) * 16;

    float acc[3][2][4][4];
#pragma unroll
    for (int z = 0; z < 3; z++)
#pragma unroll
        for (int mt = 0; mt < 2; mt++)
#pragma unroll
            for (int nt = 0; nt < 4; nt++)
#pragma unroll
                for (int i = 0; i < 4; i++) acc[z][mt][nt][i] = 0.f;

    QKV_ISSUE(0, 0)
    CP_COMMIT();
#pragma unroll 1
    for (int ch = 0; ch < 16; ch++) {
        u32 bb = (u32)(ch & 1) * QK_STAGE;
        CP_WAIT0();
        __syncthreads();
        if (ch + 1 < 16) {
            u32 nb = QK_STAGE - bb;
            QKV_ISSUE(ch + 1, nb)
            CP_COMMIT();
        }
#pragma unroll
        for (int ks = 0; ks < 4; ks++) {
            u32 ah[2][4], al[2][4];
#pragma unroll
            for (int mt = 0; mt < 2; mt++) {
                u32 off = SWZ((u32)((wr * 32 + mt * 16 + aRowL) * 128 + ks * 32 + aColL));
                ldsm4(ah[mt][0], ah[mt][1], ah[mt][2], ah[mt][3], sbase + bb + QK_AH + off);
                ldsm4(al[mt][0], al[mt][1], al[mt][2], al[mt][3], sbase + bb + QK_AL + off);
            }
#pragma unroll
            for (int z = 0; z < 3; z++) {
                u32 bh[4][2], bl[4][2];
#pragma unroll
                for (int p = 0; p < 2; p++) {
                    u32 off = SWZ((u32)((wc * 32 + p * 16 + bRowL) * 128 + ks * 32 + bColL));
                    ldsm4(bh[2*p][0], bh[2*p][1], bh[2*p+1][0], bh[2*p+1][1],
                          sbase + bb + QK_B + z * 16384 + off);
                    ldsm4(bl[2*p][0], bl[2*p][1], bl[2*p+1][0], bl[2*p+1][1],
                          sbase + bb + QK_B + z * 16384 + 8192 + off);
                }
#pragma unroll
                for (int mt = 0; mt < 2; mt++)
#pragma unroll
                    for (int nt = 0; nt < 4; nt++) {
                        hmma(acc[z][mt][nt], ah[mt], bh[nt]);
                        hmma(acc[z][mt][nt], ah[mt], bl[nt]);
                        hmma(acc[z][mt][nt], al[mt], bh[nt]);
                    }
            }
        }
    }

    // ---- epilogue per z: RMSNorm + RoPE + split stores ---------------------
    const int g = l >> 2, cp = (l & 3) * 2;
#pragma unroll 1
    for (int z = 0; z < 3; z++) {
        __syncthreads();
#pragma unroll
        for (int mt = 0; mt < 2; mt++)
#pragma unroll
            for (int nt = 0; nt < 4; nt++) {
                int row = wr * 32 + mt * 16 + g;
                int col = wc * 32 + nt * 8 + cp;
                *(float2*)&ep->outs[row][col]     = make_float2(acc[z][mt][nt][0], acc[z][mt][nt][1]);
                *(float2*)&ep->outs[row + 8][col] = make_float2(acc[z][mt][nt][2], acc[z][mt][nt][3]);
            }
        __syncthreads();
        if (z < 2 && tid < 128) {
            float ss = 0.f;
#pragma unroll
            for (int c = 0; c < 64; c++) { float v = ep->outs[tid][c]; ss = fmaf(v, v, ss); }
            ep->rstd[tid] = rsqrtf(ss * (1.0f / 64.0f) + 1e-6f);
        }
        __syncthreads();

        const float* __restrict__ nw = (z == 0) ? qw : kw;
#pragma unroll
        for (int it = 0; it < 16; it++) {
            int idx = tid + it * 256;          // pair index, 4096 total
            int row = idx >> 5, i = idx & 31;
            int c = 2 * i;
            int r = r0 + row;
            int s = r >> 1, b = r & 1;
            float v0, v1;
            if (z == 2) {
                v0 = ep->outs[row][c]; v1 = ep->outs[row][c + 1];
            } else {
                float rs = ep->rstd[row];
#pragma unroll
                for (int e = 0; e < 2; e++) {
                    int ce = c + e;
                    int j = ce & 31;
                    float cosv = rope[((size_t)s * 32 + j) * 4 + 0];
                    float sinv = rope[((size_t)s * 32 + j) * 4 + 2];
                    float a0 = ep->outs[row][j]      * rs * nw[j];
                    float a1 = ep->outs[row][j + 32] * rs * nw[j + 32];
                    float ve = (ce < 32) ? (cosv * a0 - sinv * a1) : (sinv * a0 + cosv * a1);
                    if (e == 0) v0 = ve; else v1 = ve;
                }
            }
            size_t off = ((size_t)(b * HH + h) * SQ + s) * 32 + i;
            if (z == 0) {
                u32 hp, lp;
                split2h(v0 * QS, v1 * QS, hp, lp);
                ((u32*)g_qh)[off] = hp; ((u32*)g_ql)[off] = lp;
            } else if (z == 1) {
                ((u32*)g_kh)[off] = packh(v0, v1);
            } else {
                u32 hp, lp;
                split2(v0, v1, hp, lp);
                ((u32*)g_vh)[off] = hp; ((u32*)g_vl)[off] = lp;
            }
        }
    }
}

// ---------------------------------------------------------------------------
// Kernel 2: attention. S via fp16 2-pass (Qh+Ql, K single), PV via bf16 3-pass.
// grid = (B*H, SQ/128), block = 256 (8 warps x m16 queries).
// Stage (24KB): K 0, VH 8K, VL 16K; 3 stages.
// ---------------------------------------------------------------------------
#define A_K  0
#define A_VH 8192
#define A_VL 16384
#define A_STAGE 24576
#define ATT_SMEM (3*A_STAGE)

#define ATT_ISSUE(ktv, bb)                                                      \
    _Pragma("unroll")                                                           \
    for (int q = 0; q < 2; q++) {                                               \
        int idx = tid + q * 256;                                                \
        int row = idx >> 3, c16 = (idx & 7) << 4;                               \
        u32 so = SWZ(row * 128 + c16);                                          \
        size_t go = (size_t)((ktv) * 64 + row) * 128 + c16;                     \
        cpasync16(sbase + (bb) + A_K  + so, KhP + go);                          \
        cpasync16(sbase + (bb) + A_VH + so, VhP + go);                          \
        cpasync16(sbase + (bb) + A_VL + so, VlP + go);                          \
    }

__global__ __launch_bounds__(256) void attn_hmma()
{
    extern __shared__ __align__(128) char smc[];
    const u32 sbase = smem_u32(smc);
    const int tid = threadIdx.x, l = tid & 31, w = tid >> 5;
    const int bh = blockIdx.x, qt = blockIdx.y;
    const int b = bh >> 4, h = bh & 15;

    const char* QhP = (const char*)g_qh + ((size_t)bh * SQ + qt * 128) * 128;
    const char* QlP = (const char*)g_ql + ((size_t)bh * SQ + qt * 128) * 128;
    const char* KhP = (const char*)g_kh + (size_t)bh * SQ * 128;
    const char* VhP = (const char*)g_vh + (size_t)bh * SQ * 128;
    const char* VlP = (const char*)g_vl + (size_t)bh * SQ * 128;

    // ---- stage Q tile (hi @0, lo @16384), extract A fragments --------------
#pragma unroll
    for (int q = 0; q < 4; q++) {
        int idx = tid + q * 256;
        int row = idx >> 3, c16 = (idx & 7) << 4;
        u32 so = SWZ(row * 128 + c16);
        size_t go = (size_t)row * 128 + c16;
        *(uint4*)(smc + so)         = *(const uint4*)(QhP + go);
        *(uint4*)(smc + 16384 + so) = *(const uint4*)(QlP + go);
    }
    __syncthreads();
    u32 qh[4][4], ql[4][4];
    {
        int arow = w * 16 + ((l >> 3) & 1) * 8 + (l & 7);
        int acolb = (l >> 4) * 16;
#pragma unroll
        for (int ks = 0; ks < 4; ks++) {
            u32 off = SWZ((u32)(arow * 128 + ks * 32 + acolb));
            ldsm4(qh[ks][0], qh[ks][1], qh[ks][2], qh[ks][3], sbase + off);
            ldsm4(ql[ks][0], ql[ks][1], ql[ks][2], ql[ks][3], sbase + 16384 + off);
        }
    }
    __syncthreads();

    float oacc[8][4];
#pragma unroll
    for (int nt = 0; nt < 8; nt++)
#pragma unroll
        for (int i = 0; i < 4; i++) oacc[nt][i] = 0.f;
    float lr0 = 0.f, lr1 = 0.f;

    const int brow = (l >> 4) * 8 + (l & 7);
    const int bcol = ((l >> 3) & 1) * 16;

    ATT_ISSUE(0, 0)
    CP_COMMIT();
    ATT_ISSUE(1, A_STAGE)
    CP_COMMIT();

#pragma unroll 1
    for (int kt = 0; kt < SQ / 64; kt++) {
        if (kt + 1 < SQ / 64) { CP_WAIT1(); } else { CP_WAIT0(); }
        __syncthreads();
        u32 bb = (u32)(kt % 3) * A_STAGE;
        if (kt + 2 < SQ / 64) {
            ATT_ISSUE(kt + 2, ((u32)((kt + 2) % 3)) * A_STAGE)
            CP_COMMIT();
        }

        // ---- S = Q K^T (fp16, 2 passes) ------------------------------------
        float sacc[8][4];
#pragma unroll
        for (int nt = 0; nt < 8; nt++)
#pragma unroll
            for (int i = 0; i < 4; i++) sacc[nt][i] = 0.f;
#pragma unroll
        for (int ks = 0; ks < 4; ks++) {
#pragma unroll
            for (int p = 0; p < 4; p++) {
                u32 off = SWZ((u32)((p * 16 + brow) * 128 + ks * 32 + bcol));
                u32 k0, k1, k2, k3;
                ldsm4(k0, k1, k2, k3, sbase + bb + A_K + off);
                u32 bhf0[2] = {k0, k1}, bhf1[2] = {k2, k3};
                hmma16(sacc[2*p],   qh[ks], bhf0);
                hmma16(sacc[2*p],   ql[ks], bhf0);
                hmma16(sacc[2*p+1], qh[ks], bhf1);
                hmma16(sacc[2*p+1], ql[ks], bhf1);
            }
        }

        // ---- P = exp2(S - MB), split bf16, accumulate l --------------------
        u32 pha[4][4], pla[4][4];
#pragma unroll
        for (int j = 0; j < 8; j++) {
            float p0 = ex2f(sacc[j][0] - MBc), p1 = ex2f(sacc[j][1] - MBc);
            float p2 = ex2f(sacc[j][2] - MBc), p3 = ex2f(sacc[j][3] - MBc);
            lr0 += p0 + p1; lr1 += p2 + p3;
            u32 h01, l01, h23, l23;
            split2(p0, p1, h01, l01);
            split2(p2, p3, h23, l23);
            int kk = j >> 1, o = (j & 1) * 2;
            pha[kk][o] = h01; pha[kk][o + 1] = h23;
            pla[kk][o] = l01; pla[kk][o + 1] = l23;
        }

        // ---- O += P V (bf16, 3 passes; V via ldmatrix.trans) ---------------
#pragma unroll
        for (int kk = 0; kk < 4; kk++) {
            int vrow = kk * 16 + ((l >> 3) & 1) * 8 + (l & 7);
            int vcol = (l >> 4) * 16;
#pragma unroll
            for (int pc = 0; pc < 4; pc++) {
                u32 off = SWZ((u32)(vrow * 128 + pc * 32 + vcol));
                u32 v0, v1, v2, v3, n0, n1, n2, n3;
                ldsm4t(v0, v1, v2, v3, sbase + bb + A_VH + off);
                ldsm4t(n0, n1, n2, n3, sbase + bb + A_VL + off);
                u32 vhf0[2] = {v0, v1}, vhf1[2] = {v2, v3};
                u32 vlf0[2] = {n0, n1}, vlf1[2] = {n2, n3};
                hmma(oacc[2*pc],   pha[kk], vhf0);
                hmma(oacc[2*pc],   pha[kk], vlf0);
                hmma(oacc[2*pc],   pla[kk], vhf0);
                hmma(oacc[2*pc+1], pha[kk], vhf1);
                hmma(oacc[2*pc+1], pha[kk], vlf1);
                hmma(oacc[2*pc+1], pla[kk], vhf1);
            }
        }
    }

    // ---- finalize: reduce l over quad, normalize, write split bf16 ---------
    lr0 += __shfl_xor_sync(0xffffffffu, lr0, 1);
    lr0 += __shfl_xor_sync(0xffffffffu, lr0, 2);
    lr1 += __shfl_xor_sync(0xffffffffu, lr1, 1);
    lr1 += __shfl_xor_sync(0xffffffffu, lr1, 2);
    float inv0 = 1.0f / lr0, inv1 = 1.0f / lr1;

    const int g = l >> 2, cp = (l & 3) * 2;
    const int qi0 = qt * 128 + w * 16 + g;
    u32* oh = (u32*)g_aoh;
    u32* ol = (u32*)g_aol;
#pragma unroll
    for (int nt = 0; nt < 8; nt++) {
        u32 hp, lp;
        split2(oacc[nt][0] * inv0, oacc[nt][1] * inv0, hp, lp);
        size_t off0 = (((size_t)qi0 * BB + b) * HC + h * 64 + nt * 8 + cp) >> 1;
        oh[off0] = hp; ol[off0] = lp;
        split2(oacc[nt][2] * inv1, oacc[nt][3] * inv1, hp, lp);
        size_t off1 = (((size_t)(qi0 + 8) * BB + b) * HC + h * 64 + nt * 8 + cp) >> 1;
        oh[off1] = hp; ol[off1] = lp;
    }
}

// ---------------------------------------------------------------------------
// Kernel 3: out projection (HMMA, 2-stage cp.async, single sync per stage)
// grid = (DD/64, NROW/128), block = 256
// ---------------------------------------------------------------------------
#define OFF_AH 0
#define OFF_AL 16384
#define OFF_BH 32768
#define OFF_BL 40960
#define STAGE_BYTES 49152
#define GEMM_SMEM  (2*STAGE_BYTES)

#define GEMM_ISSUE(chv, bb)                                                     \
    _Pragma("unroll")                                                           \
    for (int q = 0; q < 4; q++) {                                               \
        int idx = tid + q * 256;                                                \
        int row = idx >> 3, c16 = (idx & 7) << 4;                               \
        u32 so = SWZ(row * 128 + c16);                                          \
        size_t go = (size_t)row * 2048 + (size_t)(chv) * 128 + c16;             \
        cpasync16(sbase + (bb) + OFF_AH + so, AhP + go);                        \
        cpasync16(sbase + (bb) + OFF_AL + so, AlP + go);                        \
    }                                                                           \
    _Pragma("unroll")                                                           \
    for (int q = 0; q < 2; q++) {                                               \
        int idx = tid + q * 256;                                                \
        int row = idx >> 3, c16 = (idx & 7) << 4;                               \
        u32 so = SWZ(row * 128 + c16);                                          \
        size_t go = (size_t)row * 2048 + (size_t)(chv) * 128 + c16;             \
        cpasync16(sbase + (bb) + OFF_BH + so, BhP + go);                        \
        cpasync16(sbase + (bb) + OFF_BL + so, BlP + go);                        \
    }

__global__ __launch_bounds__(256) void outproj_hmma(float* __restrict__ out)
{
    extern __shared__ __align__(128) char smc[];
    const u32 sbase = smem_u32(smc);

    const int tid = threadIdx.x;
    const int l = tid & 31, w = tid >> 5;
    const int wr = w >> 1, wc = w & 1;
    const int n0 = blockIdx.x * 64, r0 = blockIdx.y * 128;

    const char* AhP = (const char*)(g_aoh + (size_t)r0 * HC);
    const char* AlP = (const char*)(g_aol + (size_t)r0 * HC);
    const char* BhP = (const char*)(g_wth + (size_t)3 * HC * DD + (size_t)n0 * DD);
    const char* BlP = (const char*)(g_wtl + (size_t)3 * HC * DD + (size_t)n0 * DD);

    const int aRowL = ((l >> 3) & 1) * 8 + (l & 7);
    const int aColL = (l >> 4) * 16;
    const int bRowL = (l >> 4) * 8 + (l & 7);
    const int bColL = ((l >> 3) & 1) * 16;

    float acc[2][4][4];
#pragma unroll
    for (int mt = 0; mt < 2; mt++)
#pragma unroll
        for (int nt = 0; nt < 4; nt++)
#pragma unroll
            for (int i = 0; i < 4; i++) acc[mt][nt][i] = 0.f;

    GEMM_ISSUE(0, 0)
    CP_COMMIT();
#pragma unroll 1
    for (int ch = 0; ch < 16; ch++) {
        u32 bb = (u32)(ch & 1) * STAGE_BYTES;
        CP_WAIT0();
        __syncthreads();
        if (ch + 1 < 16) {
            u32 nb = STAGE_BYTES - bb;
            GEMM_ISSUE(ch + 1, nb)
            CP_COMMIT();
        }
#pragma unroll
        for (int ks = 0; ks < 4; ks++) {
            u32 ah[2][4], al[2][4], bh[4][2], bl[4][2];
#pragma unroll
            for (int mt = 0; mt < 2; mt++) {
                u32 off = SWZ((u32)((wr * 32 + mt * 16 + aRowL) * 128 + ks * 32 + aColL));
                ldsm4(ah[mt][0], ah[mt][1], ah[mt][2], ah[mt][3], sbase + bb + OFF_AH + off);
                ldsm4(al[mt][0], al[mt][1], al[mt][2], al[mt][3], sbase + bb + OFF_AL + off);
            }
#pragma unroll
            for (int p = 0; p < 2; p++) {
                u32 off = SWZ((u32)((wc * 32 + p * 16 + bRowL) * 128 + ks * 32 + bColL));
                ldsm4(bh[2*p][0], bh[2*p][1], bh[2*p+1][0], bh[2*p+1][1], sbase + bb + OFF_BH + off);
                ldsm4(bl[2*p][0], bl[2*p][1], bl[2*p+1][0], bl[2*p+1][1], sbase + bb + OFF_BL + off);
            }
#pragma unroll
            for (int mt = 0; mt < 2; mt++)
#pragma unroll
                for (int nt = 0; nt < 4; nt++) {
                    hmma(acc[mt][nt], ah[mt], bh[nt]);
                    hmma(acc[mt][nt], ah[mt], bl[nt]);
                    hmma(acc[mt][nt], al[mt], bh[nt]);
                }
        }
    }

    const int g = l >> 2, cp = (l & 3) * 2;
#pragma unroll
    for (int mt = 0; mt < 2; mt++)
#pragma unroll
        for (int nt = 0; nt < 4; nt++) {
            int row = r0 + wr * 32 + mt * 16 + g;
            int col = n0 + wc * 32 + nt * 8 + cp;
            *(float2*)&out[(size_t)row * DD + col] =
                make_float2(acc[mt][nt][0], acc[mt][nt][1]);
            *(float2*)&out[(size_t)(row + 8) * DD + col] =
                make_float2(acc[mt][nt][2], acc[mt][nt][3]);
        }
}

// ---------------------------------------------------------------------------
extern "C" void kernel_launch(void* const* d_in, const int* in_sizes, int n_in,
                              void* d_out, int out_size)
{
    (void)in_sizes; (void)n_in; (void)out_size;
    const float* x    = (const float*)d_in[0];
    const float* rope = (const float*)d_in[1];
    const float* Wq   = (const float*)d_in[2];
    const float* Wk   = (const float*)d_in[3];
    const float* Wv   = (const float*)d_in[4];
    const float* qw   = (const float*)d_in[5];
    const float* kw   = (const float*)d_in[6];
    const float* Wout = (const float*)d_in[7];
    float* out = (float*)d_out;

    static int configured = 0;
    if (!configured) {
        cudaFuncSetAttribute(qkv_hmma,
            cudaFuncAttributeMaxDynamicSharedMemorySize, QKV_SMEM);
        cudaFuncSetAttribute(attn_hmma,
            cudaFuncAttributeMaxDynamicSharedMemorySize, ATT_SMEM);
        cudaFuncSetAttribute(outproj_hmma,
            cudaFuncAttributeMaxDynamicSharedMemorySize, GEMM_SMEM);
        configured = 1;
    }

    conv_x<<<NROW * DD / 4 / 256, 256>>>(x);
    prep_w<<<dim3(32, 32, 4), 256>>>(Wq, Wk, Wv, Wout);

    qkv_hmma<<<dim3(HH, NROW / 128), 256, QKV_SMEM>>>(rope, qw, kw);

    attn_hmma<<<dim3(BB * HH, SQ / 128), 256, ATT_SMEM>>>();

    outproj_hmma<<<dim3(DD / 64, NROW / 128), 256, GEMM_SMEM>>>(out);
}

// round 17
// speedup vs baseline: 1.8425x; 1.8425x over previous
#include <cuda_runtime.h>
#include <cuda_bf16.h>
#include <cuda_fp16.h>
#include <math.h>
#include <stdint.h>

#define SQ 2048
#define BB 2
#define DD 1024
#define HH 16
#define CC 64
#define HC 1024
#define NROW 4096

typedef unsigned long long ull;
typedef unsigned int u32;

__device__ __forceinline__ float ex2f(float x) {
    float y; asm("ex2.approx.f32 %0, %1;" : "=f"(y) : "f"(x)); return y;
}
__device__ __forceinline__ u32 smem_u32(const void* p) {
    u32 a;
    asm("{ .reg .u64 t; cvta.to.shared.u64 t, %1; cvt.u32.u64 %0, t; }"
        : "=r"(a) : "l"(p));
    return a;
}
__device__ __forceinline__ void ldsm4(u32 &r0, u32 &r1, u32 &r2, u32 &r3, u32 addr) {
    asm volatile("ldmatrix.sync.aligned.m8n8.x4.shared.b16 {%0,%1,%2,%3}, [%4];"
                 : "=r"(r0), "=r"(r1), "=r"(r2), "=r"(r3) : "r"(addr));
}
__device__ __forceinline__ void ldsm4t(u32 &r0, u32 &r1, u32 &r2, u32 &r3, u32 addr) {
    asm volatile("ldmatrix.sync.aligned.m8n8.x4.trans.shared.b16 {%0,%1,%2,%3}, [%4];"
                 : "=r"(r0), "=r"(r1), "=r"(r2), "=r"(r3) : "r"(addr));
}
// bf16 MMA
__device__ __forceinline__ void hmma(float* d, const u32* a, const u32* b) {
    asm volatile(
        "mma.sync.aligned.m16n8k16.row.col.f32.bf16.bf16.f32 "
        "{%0,%1,%2,%3}, {%4,%5,%6,%7}, {%8,%9}, {%0,%1,%2,%3};"
        : "+f"(d[0]), "+f"(d[1]), "+f"(d[2]), "+f"(d[3])
        : "r"(a[0]), "r"(a[1]), "r"(a[2]), "r"(a[3]), "r"(b[0]), "r"(b[1]));
}
// fp16 MMA
__device__ __forceinline__ void hmma16(float* d, const u32* a, const u32* b) {
    asm volatile(
        "mma.sync.aligned.m16n8k16.row.col.f32.f16.f16.f32 "
        "{%0,%1,%2,%3}, {%4,%5,%6,%7}, {%8,%9}, {%0,%1,%2,%3};"
        : "+f"(d[0]), "+f"(d[1]), "+f"(d[2]), "+f"(d[3])
        : "r"(a[0]), "r"(a[1]), "r"(a[2]), "r"(a[3]), "r"(b[0]), "r"(b[1]));
}
__device__ __forceinline__ void cpasync16(u32 saddr, const void* g) {
    asm volatile("cp.async.cg.shared.global [%0], [%1], 16;"
                 :: "r"(saddr), "l"(g) : "memory");
}
#define CP_COMMIT() asm volatile("cp.async.commit_group;" ::: "memory")
#define CP_WAIT1()  asm volatile("cp.async.wait_group 1;" ::: "memory")
#define CP_WAIT0()  asm volatile("cp.async.wait_group 0;" ::: "memory")

#define SWZ(o) ((o) ^ (((o) >> 3) & 0x70))

// bf16 hi/lo split
__device__ __forceinline__ void split2(float a, float b, u32 &hp, u32 &lp) {
    __nv_bfloat16 ha = __float2bfloat16_rn(a), hb = __float2bfloat16_rn(b);
    float ra = a - __bfloat162float(ha);
    float rb = b - __bfloat162float(hb);
    __nv_bfloat16 la = __float2bfloat16_rn(ra), lb = __float2bfloat16_rn(rb);
    hp = (u32)__bfloat16_as_ushort(ha) | ((u32)__bfloat16_as_ushort(hb) << 16);
    lp = (u32)__bfloat16_as_ushort(la) | ((u32)__bfloat16_as_ushort(lb) << 16);
}
// fp16 hi/lo split
__device__ __forceinline__ void split2h(float a, float b, u32 &hp, u32 &lp) {
    __half ha = __float2half_rn(a), hb = __float2half_rn(b);
    float ra = a - __half2float(ha);
    float rb = b - __half2float(hb);
    __half la = __float2half_rn(ra), lb = __float2half_rn(rb);
    hp = (u32)__half_as_ushort(ha) | ((u32)__half_as_ushort(hb) << 16);
    lp = (u32)__half_as_ushort(la) | ((u32)__half_as_ushort(lb) << 16);
}
__device__ __forceinline__ u32 packh(float a, float b) {
    __half ha = __float2half_rn(a), hb = __float2half_rn(b);
    return (u32)__half_as_ushort(ha) | ((u32)__half_as_ushort(hb) << 16);
}

// ---------------- scratch (allocation-free) ---------------------------------
__device__ __nv_bfloat16 g_xh[(size_t)NROW*DD];
__device__ __nv_bfloat16 g_xl[(size_t)NROW*DD];
__device__ __nv_bfloat16 g_wth[(size_t)4*HC*DD];   // z: 0=q 1=k 2=v 3=out, [N][K]
__device__ __nv_bfloat16 g_wtl[(size_t)4*HC*DD];
__device__ __half g_qh[(size_t)BB*HH*SQ*CC];       // fp16 hi, pre-scaled by QS
__device__ __half g_ql[(size_t)BB*HH*SQ*CC];       // fp16 lo
__device__ __half g_kh[(size_t)BB*HH*SQ*CC];       // fp16 single
__device__ __nv_bfloat16 g_vh[(size_t)BB*HH*SQ*CC];
__device__ __nv_bfloat16 g_vl[(size_t)BB*HH*SQ*CC];
__device__ __nv_bfloat16 g_aoh[(size_t)NROW*HC];
__device__ __nv_bfloat16 g_aol[(size_t)NROW*HC];

#define QS 0.18033688011112042f   /* 0.125 * log2(e) */
#define MBc 23.083120654223414f   /* 16 * log2(e) */

// ---------------- prep kernels ----------------------------------------------
__global__ __launch_bounds__(256) void conv_x(const float* __restrict__ x)
{
    int i = blockIdx.x * 256 + threadIdx.x;
    float4 v = ((const float4*)x)[i];
    u32 h01, l01, h23, l23;
    split2(v.x, v.y, h01, l01);
    split2(v.z, v.w, h23, l23);
    ((uint2*)g_xh)[i] = make_uint2(h01, h23);
    ((uint2*)g_xl)[i] = make_uint2(l01, l23);
}

__global__ __launch_bounds__(256) void prep_w(
    const float* __restrict__ Wq, const float* __restrict__ Wk,
    const float* __restrict__ Wv, const float* __restrict__ Wo)
{
    const int z = blockIdx.z;
    const float* __restrict__ W = (z == 0) ? Wq : (z == 1) ? Wk : (z == 2) ? Wv : Wo;
    const int n0 = blockIdx.x * 32, k0 = blockIdx.y * 32;
    __shared__ float t[32][33];
    const int c = threadIdx.x & 31, r8 = threadIdx.x >> 5;
#pragma unroll
    for (int rr = 0; rr < 4; rr++) {
        int r = r8 + rr * 8;
        t[c][r] = W[(size_t)(k0 + r) * HC + n0 + c];
    }
    __syncthreads();
    __nv_bfloat16* oh = g_wth + (size_t)z * HC * DD;
    __nv_bfloat16* ol = g_wtl + (size_t)z * HC * DD;
#pragma unroll
    for (int rr = 0; rr < 4; rr++) {
        int r = r8 + rr * 8;
        float v = t[r][c];
        __nv_bfloat16 h = __float2bfloat16_rn(v);
        __nv_bfloat16 l = __float2bfloat16_rn(v - __bfloat162float(h));
        size_t o = (size_t)(n0 + r) * DD + k0 + c;
        oh[o] = h; ol[o] = l;
    }
}

// ---------------------------------------------------------------------------
// HMMA GEMM core, cp.async double-buffered (round-14 proven). BM=128, BN=64,
// BK=64, 8 warps 4m x 2n.
// ---------------------------------------------------------------------------
#define OFF_AH 0
#define OFF_AL 16384
#define OFF_BH 32768
#define OFF_BL 40960
#define STAGE_BYTES 49152
#define GEMM_SMEM  (2*STAGE_BYTES)

struct EpiSmem { float outs[128][66]; float rstd[128]; };

#define GEMM_ISSUE(chv, bb)                                                     \
    _Pragma("unroll")                                                           \
    for (int q = 0; q < 4; q++) {                                               \
        int idx = tid + q * 256;                                                \
        int row = idx >> 3, c16 = (idx & 7) << 4;                               \
        u32 so = SWZ(row * 128 + c16);                                          \
        size_t go = (size_t)row * 2048 + (size_t)(chv) * 128 + c16;             \
        cpasync16(sbase + (bb) + OFF_AH + so, AhP + go);                        \
        cpasync16(sbase + (bb) + OFF_AL + so, AlP + go);                        \
    }                                                                           \
    _Pragma("unroll")                                                           \
    for (int q = 0; q < 2; q++) {                                               \
        int idx = tid + q * 256;                                                \
        int row = idx >> 3, c16 = (idx & 7) << 4;                               \
        u32 so = SWZ(row * 128 + c16);                                          \
        size_t go = (size_t)row * 2048 + (size_t)(chv) * 128 + c16;             \
        cpasync16(sbase + (bb) + OFF_BH + so, BhP + go);                        \
        cpasync16(sbase + (bb) + OFF_BL + so, BlP + go);                        \
    }

#define COMPUTE_CHUNK(bb)                                                       \
    _Pragma("unroll")                                                           \
    for (int ks = 0; ks < 4; ks++) {                                            \
        u32 ah[2][4], al[2][4], bh[4][2], bl[4][2];                             \
        _Pragma("unroll")                                                       \
        for (int mt = 0; mt < 2; mt++) {                                        \
            u32 off = SWZ((u32)((wr * 32 + mt * 16 + aRowL) * 128 + ks * 32 + aColL)); \
            ldsm4(ah[mt][0], ah[mt][1], ah[mt][2], ah[mt][3], sbase + (bb) + OFF_AH + off); \
            ldsm4(al[mt][0], al[mt][1], al[mt][2], al[mt][3], sbase + (bb) + OFF_AL + off); \
        }                                                                       \
        _Pragma("unroll")                                                       \
        for (int p = 0; p < 2; p++) {                                           \
            u32 off = SWZ((u32)((wc * 32 + p * 16 + bRowL) * 128 + ks * 32 + bColL)); \
            ldsm4(bh[2*p][0], bh[2*p][1], bh[2*p+1][0], bh[2*p+1][1], sbase + (bb) + OFF_BH + off); \
            ldsm4(bl[2*p][0], bl[2*p][1], bl[2*p+1][0], bl[2*p+1][1], sbase + (bb) + OFF_BL + off); \
        }                                                                       \
        _Pragma("unroll")                                                       \
        for (int mt = 0; mt < 2; mt++)                                          \
            _Pragma("unroll")                                                   \
            for (int nt = 0; nt < 4; nt++) {                                    \
                hmma(acc[mt][nt], ah[mt], bh[nt]);                              \
                hmma(acc[mt][nt], ah[mt], bl[nt]);                              \
                hmma(acc[mt][nt], al[mt], bh[nt]);                              \
            }                                                                   \
    }

#define GEMM_MAINLOOP()                                                         \
    GEMM_ISSUE(0, 0)                                                            \
    CP_COMMIT();                                                                \
    _Pragma("unroll 1")                                                         \
    for (int ch = 0; ch < 16; ch++) {                                           \
        u32 bb = (u32)(ch & 1) * STAGE_BYTES;                                   \
        if (ch + 1 < 16) {                                                      \
            u32 nb = STAGE_BYTES - bb;                                          \
            GEMM_ISSUE(ch + 1, nb)                                              \
            CP_COMMIT();                                                        \
            CP_WAIT1();                                                         \
        } else {                                                                \
            CP_WAIT0();                                                         \
        }                                                                       \
        __syncthreads();                                                        \
        COMPUTE_CHUNK(bb)                                                       \
        __syncthreads();                                                        \
    }

// ---------------- kernel 1: QKV + RMSNorm + RoPE -> mixed split stores ------
// grid = (HH, NROW/128, 3), block = 256, dynamic smem 96KB
__global__ __launch_bounds__(256) void qkv_hmma(
    const float* __restrict__ rope, const float* __restrict__ qw,
    const float* __restrict__ kw)
{
    extern __shared__ __align__(128) char smc[];
    EpiSmem* ep = (EpiSmem*)smc;
    const u32 sbase = smem_u32(smc);

    const int tid = threadIdx.x;
    const int l = tid & 31, w = tid >> 5;
    const int wr = w >> 1, wc = w & 1;
    const int h = blockIdx.x, r0 = blockIdx.y * 128, z = blockIdx.z;
    const int n0 = h * CC;

    const char* AhP = (const char*)(g_xh + (size_t)r0 * DD);
    const char* AlP = (const char*)(g_xl + (size_t)r0 * DD);
    const char* BhP = (const char*)(g_wth + (size_t)z * HC * DD + (size_t)n0 * DD);
    const char* BlP = (const char*)(g_wtl + (size_t)z * HC * DD + (size_t)n0 * DD);

    const int aRowL = ((l >> 3) & 1) * 8 + (l & 7);
    const int aColL = (l >> 4) * 16;
    const int bRowL = (l >> 4) * 8 + (l & 7);
    const int bColL = ((l >> 3) & 1) * 16;

    float acc[2][4][4];
#pragma unroll
    for (int mt = 0; mt < 2; mt++)
#pragma unroll
        for (int nt = 0; nt < 4; nt++)
#pragma unroll
            for (int i = 0; i < 4; i++) acc[mt][nt][i] = 0.f;

    GEMM_MAINLOOP()

    // ---- epilogue: RMSNorm + RoPE + mixed-precision scatter ----------------
    const int g = l >> 2, cp = (l & 3) * 2;
#pragma unroll
    for (int mt = 0; mt < 2; mt++)
#pragma unroll
        for (int nt = 0; nt < 4; nt++) {
            int row = wr * 32 + mt * 16 + g;
            int col = wc * 32 + nt * 8 + cp;
            *(float2*)&ep->outs[row][col]     = make_float2(acc[mt][nt][0], acc[mt][nt][1]);
            *(float2*)&ep->outs[row + 8][col] = make_float2(acc[mt][nt][2], acc[mt][nt][3]);
        }
    __syncthreads();

    if (z < 2 && tid < 128) {
        float ss = 0.f;
#pragma unroll
        for (int c = 0; c < 64; c++) { float v = ep->outs[tid][c]; ss = fmaf(v, v, ss); }
        ep->rstd[tid] = rsqrtf(ss * (1.0f / 64.0f) + 1e-6f);
    }
    __syncthreads();

    const float* __restrict__ nw = (z == 0) ? qw : kw;
#pragma unroll
    for (int it = 0; it < 16; it++) {
        int idx = tid + it * 256;          // pair index, 4096 total
        int row = idx >> 5, i = idx & 31;
        int c = 2 * i;
        int r = r0 + row;
        int s = r >> 1, b = r & 1;
        float v0, v1;
        if (z == 2) {
            v0 = ep->outs[row][c]; v1 = ep->outs[row][c + 1];
        } else {
            float rs = ep->rstd[row];
#pragma unroll
            for (int e = 0; e < 2; e++) {
                int ce = c + e;
                int j = ce & 31;
                float cosv = rope[((size_t)s * 32 + j) * 4 + 0];
                float sinv = rope[((size_t)s * 32 + j) * 4 + 2];
                float a0 = ep->outs[row][j]      * rs * nw[j];
                float a1 = ep->outs[row][j + 32] * rs * nw[j + 32];
                float ve = (ce < 32) ? (cosv * a0 - sinv * a1) : (sinv * a0 + cosv * a1);
                if (e == 0) v0 = ve; else v1 = ve;
            }
        }
        size_t off = ((size_t)(b * HH + h) * SQ + s) * 32 + i;
        if (z == 0) {
            u32 hp, lp;
            split2h(v0 * QS, v1 * QS, hp, lp);
            ((u32*)g_qh)[off] = hp; ((u32*)g_ql)[off] = lp;
        } else if (z == 1) {
            ((u32*)g_kh)[off] = packh(v0, v1);
        } else {
            u32 hp, lp;
            split2(v0, v1, hp, lp);
            ((u32*)g_vh)[off] = hp; ((u32*)g_vl)[off] = lp;
        }
    }
}

// ---------------------------------------------------------------------------
// Kernel 2: attention. S via fp16 2-pass (Qh+Ql vs single-fp16 K, 1 LDSM/step),
// PV via bf16 3-pass. Round-14 2-stage double-buffer structure.
// grid = (B*H, SQ/128), block = 256 (8 warps x m16 queries).
// Stage (24KB): K 0, VH 8K, VL 16K; 2 stages = 48KB.
// ---------------------------------------------------------------------------
#define A_K  0
#define A_VH 8192
#define A_VL 16384
#define A_STAGE 24576
#define ATT_SMEM (2*A_STAGE)

#define ATT_ISSUE(ktv, bb)                                                      \
    _Pragma("unroll")                                                           \
    for (int q = 0; q < 2; q++) {                                               \
        int idx = tid + q * 256;                                                \
        int row = idx >> 3, c16 = (idx & 7) << 4;                               \
        u32 so = SWZ(row * 128 + c16);                                          \
        size_t go = (size_t)((ktv) * 64 + row) * 128 + c16;                     \
        cpasync16(sbase + (bb) + A_K  + so, KhP + go);                          \
        cpasync16(sbase + (bb) + A_VH + so, VhP + go);                          \
        cpasync16(sbase + (bb) + A_VL + so, VlP + go);                          \
    }

__global__ __launch_bounds__(256, 2) void attn_hmma()
{
    extern __shared__ __align__(128) char smc[];
    const u32 sbase = smem_u32(smc);
    const int tid = threadIdx.x, l = tid & 31, w = tid >> 5;
    const int bh = blockIdx.x, qt = blockIdx.y;
    const int b = bh >> 4, h = bh & 15;

    const char* QhP = (const char*)g_qh + ((size_t)bh * SQ + qt * 128) * 128;
    const char* QlP = (const char*)g_ql + ((size_t)bh * SQ + qt * 128) * 128;
    const char* KhP = (const char*)g_kh + (size_t)bh * SQ * 128;
    const char* VhP = (const char*)g_vh + (size_t)bh * SQ * 128;
    const char* VlP = (const char*)g_vl + (size_t)bh * SQ * 128;

    // ---- stage Q tile (hi @0, lo @16K within the 48KB region), get frags ---
#pragma unroll
    for (int q = 0; q < 4; q++) {
        int idx = tid + q * 256;
        int row = idx >> 3, c16 = (idx & 7) << 4;
        u32 so = SWZ(row * 128 + c16);
        size_t go = (size_t)row * 128 + c16;
        *(uint4*)(smc + so)         = *(const uint4*)(QhP + go);
        *(uint4*)(smc + 16384 + so) = *(const uint4*)(QlP + go);
    }
    __syncthreads();
    u32 qh[4][4], ql[4][4];
    {
        int arow = w * 16 + ((l >> 3) & 1) * 8 + (l & 7);
        int acolb = (l >> 4) * 16;
#pragma unroll
        for (int ks = 0; ks < 4; ks++) {
            u32 off = SWZ((u32)(arow * 128 + ks * 32 + acolb));
            ldsm4(qh[ks][0], qh[ks][1], qh[ks][2], qh[ks][3], sbase + off);
            ldsm4(ql[ks][0], ql[ks][1], ql[ks][2], ql[ks][3], sbase + 16384 + off);
        }
    }
    __syncthreads();

    float oacc[8][4];
#pragma unroll
    for (int nt = 0; nt < 8; nt++)
#pragma unroll
        for (int i = 0; i < 4; i++) oacc[nt][i] = 0.f;
    float lr0 = 0.f, lr1 = 0.f;

    const int brow = (l >> 4) * 8 + (l & 7);
    const int bcol = ((l >> 3) & 1) * 16;

    ATT_ISSUE(0, 0)
    CP_COMMIT();

#pragma unroll 1
    for (int kt = 0; kt < SQ / 64; kt++) {
        u32 bb = (u32)(kt & 1) * A_STAGE;
        if (kt + 1 < SQ / 64) {
            u32 nb = A_STAGE - bb;
            ATT_ISSUE(kt + 1, nb)
            CP_COMMIT();
            CP_WAIT1();
        } else {
            CP_WAIT0();
        }
        __syncthreads();

        // ---- S = Q K^T (fp16, 2 passes, 1 LDSM per step) -------------------
        float sacc[8][4];
#pragma unroll
        for (int nt = 0; nt < 8; nt++)
#pragma unroll
            for (int i = 0; i < 4; i++) sacc[nt][i] = 0.f;
#pragma unroll
        for (int ks = 0; ks < 4; ks++) {
#pragma unroll
            for (int p = 0; p < 4; p++) {
                u32 off = SWZ((u32)((p * 16 + brow) * 128 + ks * 32 + bcol));
                u32 k0, k1, k2, k3;
                ldsm4(k0, k1, k2, k3, sbase + bb + A_K + off);
                u32 bhf0[2] = {k0, k1}, bhf1[2] = {k2, k3};
                hmma16(sacc[2*p],   qh[ks], bhf0);
                hmma16(sacc[2*p],   ql[ks], bhf0);
                hmma16(sacc[2*p+1], qh[ks], bhf1);
                hmma16(sacc[2*p+1], ql[ks], bhf1);
            }
        }

        // ---- P = exp2(S - MB), split bf16, accumulate l --------------------
        u32 pha[4][4], pla[4][4];
#pragma unroll
        for (int j = 0; j < 8; j++) {
            float p0 = ex2f(sacc[j][0] - MBc), p1 = ex2f(sacc[j][1] - MBc);
            float p2 = ex2f(sacc[j][2] - MBc), p3 = ex2f(sacc[j][3] - MBc);
            lr0 += p0 + p1; lr1 += p2 + p3;
            u32 h01, l01, h23, l23;
            split2(p0, p1, h01, l01);
            split2(p2, p3, h23, l23);
            int kk = j >> 1, o = (j & 1) * 2;
            pha[kk][o] = h01; pha[kk][o + 1] = h23;
            pla[kk][o] = l01; pla[kk][o + 1] = l23;
        }

        // ---- O += P V (bf16, 3 passes; V via ldmatrix.trans) ---------------
#pragma unroll
        for (int kk = 0; kk < 4; kk++) {
            int vrow = kk * 16 + ((l >> 3) & 1) * 8 + (l & 7);
            int vcol = (l >> 4) * 16;
#pragma unroll
            for (int pc = 0; pc < 4; pc++) {
                u32 off = SWZ((u32)(vrow * 128 + pc * 32 + vcol));
                u32 v0, v1, v2, v3, n0, n1, n2, n3;
                ldsm4t(v0, v1, v2, v3, sbase + bb + A_VH + off);
                ldsm4t(n0, n1, n2, n3, sbase + bb + A_VL + off);
                u32 vhf0[2] = {v0, v1}, vhf1[2] = {v2, v3};
                u32 vlf0[2] = {n0, n1}, vlf1[2] = {n2, n3};
                hmma(oacc[2*pc],   pha[kk], vhf0);
                hmma(oacc[2*pc],   pha[kk], vlf0);
                hmma(oacc[2*pc],   pla[kk], vhf0);
                hmma(oacc[2*pc+1], pha[kk], vhf1);
                hmma(oacc[2*pc+1], pha[kk], vlf1);
                hmma(oacc[2*pc+1], pla[kk], vhf1);
            }
        }
        __syncthreads();
    }

    // ---- finalize: reduce l over quad, normalize, write split bf16 ---------
    lr0 += __shfl_xor_sync(0xffffffffu, lr0, 1);
    lr0 += __shfl_xor_sync(0xffffffffu, lr0, 2);
    lr1 += __shfl_xor_sync(0xffffffffu, lr1, 1);
    lr1 += __shfl_xor_sync(0xffffffffu, lr1, 2);
    float inv0 = 1.0f / lr0, inv1 = 1.0f / lr1;

    const int g = l >> 2, cp = (l & 3) * 2;
    const int qi0 = qt * 128 + w * 16 + g;
    u32* oh = (u32*)g_aoh;
    u32* ol = (u32*)g_aol;
#pragma unroll
    for (int nt = 0; nt < 8; nt++) {
        u32 hp, lp;
        split2(oacc[nt][0] * inv0, oacc[nt][1] * inv0, hp, lp);
        size_t off0 = (((size_t)qi0 * BB + b) * HC + h * 64 + nt * 8 + cp) >> 1;
        oh[off0] = hp; ol[off0] = lp;
        split2(oacc[nt][2] * inv1, oacc[nt][3] * inv1, hp, lp);
        size_t off1 = (((size_t)(qi0 + 8) * BB + b) * HC + h * 64 + nt * 8 + cp) >> 1;
        oh[off1] = hp; ol[off1] = lp;
    }
}

// ---------------- kernel 3: out projection (HMMA, pipelined) ----------------
// grid = (DD/64, NROW/128), block = 256, dynamic smem 96KB
__global__ __launch_bounds__(256) void outproj_hmma(float* __restrict__ out)
{
    extern __shared__ __align__(128) char smc[];
    const u32 sbase = smem_u32(smc);

    const int tid = threadIdx.x;
    const int l = tid & 31, w = tid >> 5;
    const int wr = w >> 1, wc = w & 1;
    const int n0 = blockIdx.x * 64, r0 = blockIdx.y * 128;

    const char* AhP = (const char*)(g_aoh + (size_t)r0 * HC);
    const char* AlP = (const char*)(g_aol + (size_t)r0 * HC);
    const char* BhP = (const char*)(g_wth + (size_t)3 * HC * DD + (size_t)n0 * DD);
    const char* BlP = (const char*)(g_wtl + (size_t)3 * HC * DD + (size_t)n0 * DD);

    const int aRowL = ((l >> 3) & 1) * 8 + (l & 7);
    const int aColL = (l >> 4) * 16;
    const int bRowL = (l >> 4) * 8 + (l & 7);
    const int bColL = ((l >> 3) & 1) * 16;

    float acc[2][4][4];
#pragma unroll
    for (int mt = 0; mt < 2; mt++)
#pragma unroll
        for (int nt = 0; nt < 4; nt++)
#pragma unroll
            for (int i = 0; i < 4; i++) acc[mt][nt][i] = 0.f;

    GEMM_MAINLOOP()

    const int g = l >> 2, cp = (l & 3) * 2;
#pragma unroll
    for (int mt = 0; mt < 2; mt++)
#pragma unroll
        for (int nt = 0; nt < 4; nt++) {
            int row = r0 + wr * 32 + mt * 16 + g;
            int col = n0 + wc * 32 + nt * 8 + cp;
            *(float2*)&out[(size_t)row * DD + col] =
                make_float2(acc[mt][nt][0], acc[mt][nt][1]);
            *(float2*)&out[(size_t)(row + 8) * DD + col] =
                make_float2(acc[mt][nt][2], acc[mt][nt][3]);
        }
}

// ---------------------------------------------------------------------------
extern "C" void kernel_launch(void* const* d_in, const int* in_sizes, int n_in,
                              void* d_out, int out_size)
{
    (void)in_sizes; (void)n_in; (void)out_size;
    const float* x    = (const float*)d_in[0];
    const float* rope = (const float*)d_in[1];
    const float* Wq   = (const float*)d_in[2];
    const float* Wk   = (const float*)d_in[3];
    const float* Wv   = (const float*)d_in[4];
    const float* qw   = (const float*)d_in[5];
    const float* kw   = (const float*)d_in[6];
    const float* Wout = (const float*)d_in[7];
    float* out = (float*)d_out;

    static int configured = 0;
    if (!configured) {
        cudaFuncSetAttribute(qkv_hmma,
            cudaFuncAttributeMaxDynamicSharedMemorySize, GEMM_SMEM);
        cudaFuncSetAttribute(attn_hmma,
            cudaFuncAttributeMaxDynamicSharedMemorySize, ATT_SMEM);
        cudaFuncSetAttribute(outproj_hmma,
            cudaFuncAttributeMaxDynamicSharedMemorySize, GEMM_SMEM);
        configured = 1;
    }

    conv_x<<<NROW * DD / 4 / 256, 256>>>(x);
    prep_w<<<dim3(32, 32, 4), 256>>>(Wq, Wk, Wv, Wout);

    qkv_hmma<<<dim3(HH, NROW / 128, 3), 256, GEMM_SMEM>>>(rope, qw, kw);

    attn_hmma<<<dim3(BB * HH, SQ / 128), 256, ATT_SMEM>>>();

    outproj_hmma<<<dim3(DD / 64, NROW / 128), 256, GEMM_SMEM>>>(out);
}